// round 14
// baseline (speedup 1.0000x reference)
#include <cuda_runtime.h>
#include <cuda_fp16.h>
#include <math.h>

// Problem constants (fixed shapes)
#define IMG_N     512
#define N_ANGLES  512
#define DET_COUNT 512
#define N_SAMP    256

// u8 quad table, row-major. Table coord tx in [0,528): floor-cell real-x = tx - 6.
// quad(ty,tx) = bytes {b00, b01, b10, b11} = round(P*255) of the 2x2 corners,
// P = image with zeros outside [0,512)^2. Nonzero quads live at tx in [5,517];
// the >=5-cell zero guard on each side absorbs clip slack (max 1 sample step
// = 2.83 cells past the clip window) with no per-sample clamp or mask.
#define TAB_N     528
#define OFF       6.0f
__device__ unsigned int g_quad[TAB_N * TAB_N];

__global__ void build_quad_kernel(const float* __restrict__ img) {
    int i = blockIdx.x * blockDim.x + threadIdx.x;
    if (i >= TAB_N * TAB_N) return;
    int tx = i % TAB_N;
    int ty = i / TAB_N;
    int ix = tx - 6;                  // real-coord floor cell
    int iy = ty - 6;
    unsigned int b[2][2];
    #pragma unroll
    for (int r = 0; r < 2; ++r)
        #pragma unroll
        for (int c = 0; c < 2; ++c) {
            int ry = iy + r;
            int rx = ix + c;
            float v = ((unsigned)ry < (unsigned)IMG_N && (unsigned)rx < (unsigned)IMG_N)
                          ? __ldg(&img[ry * IMG_N + rx]) : 0.0f;
            b[r][c] = __float2uint_rn(v * 255.0f);
        }
    g_quad[i] = b[0][0] | (b[0][1] << 8) | (b[1][0] << 16) | (b[1][1] << 24);
}

// Warp shape: 8 detectors x 4 sample-phases. lane = p*8 + d_off.
// Thread accumulates samples s ≡ p (mod 4); butterfly-reduce over phases at end.
__global__ __launch_bounds__(256)
void radon_kernel(float* __restrict__ out) {
    int idx  = blockIdx.x * blockDim.x + threadIdx.x;   // 0 .. 4*512*512-1
    int lane = idx & 31;
    int w    = idx >> 5;
    int p    = lane >> 3;
    int a    = w >> 6;
    int d    = ((w & 63) << 3) | (lane & 7);

    const float PI_F    = 3.14159265358979323846f;
    const float SQRT2_F = 1.41421356237309504880f;

    float ang = a * (PI_F / (N_ANGLES - 1)) + 0.5f * PI_F;
    float sa, ca;
    sincosf(ang, &sa, &ca);

    float sx = -1.0f + d * (2.0f / (DET_COUNT - 1));
    const float sy = -SQRT2_F;

    float rsx = sx * ca - sy * sa;
    float rsy = sx * sa + sy * ca;
    float rdx = 2.0f * sy * sa;
    float rdy = -2.0f * sy * ca;

    const float HALF = 0.5f * (IMG_N - 1);   // 255.5
    float Ax = (rsx + 1.0f) * HALF + OFF;
    float Ay = (rsy + 1.0f) * HALF + OFF;
    float Bx = rdx * (HALF / N_SAMP);
    float By = rdy * (HALF / N_SAMP);

    // Clip to nonzero region: real x in (-1,512) => X in (5, 518) table coords.
    float slo = 0.0f, shi = (float)N_SAMP;
    {
        const float LO = 5.0f, HI = 518.0f;
        if (fabsf(Bx) > 1e-12f) {
            float inv = __fdividef(1.0f, Bx);
            float t1 = (LO - Ax) * inv;
            float t2 = (HI - Ax) * inv;
            slo = fmaxf(slo, fminf(t1, t2));
            shi = fminf(shi, fmaxf(t1, t2));
        } else if (Ax <= LO || Ax >= HI) {
            shi = slo;
        }
        if (fabsf(By) > 1e-12f) {
            float inv = __fdividef(1.0f, By);
            float t1 = (LO - Ay) * inv;
            float t2 = (HI - Ay) * inv;
            slo = fmaxf(slo, fminf(t1, t2));
            shi = fminf(shi, fmaxf(t1, t2));
        } else if (Ay <= LO || Ay >= HI) {
            shi = slo;
        }
    }
    int s0 = max(0, (int)ceilf(slo - 1.0f));
    int s1 = min(N_SAMP, (int)floorf(shi + 1.0f) + 1);

    // First sample for this phase: s ≡ p (mod 4), s >= s0
    int s_start = s0 + ((p - s0) & 3);

    // Incremental ray position (step = 4 samples)
    float X = fmaf((float)s_start, Bx, Ax);
    float Y = fmaf((float)s_start, By, Ay);
    float Bx4 = 4.0f * Bx;
    float By4 = 4.0f * By;

    const unsigned int MAGIC = 0x64646464u;       // fp16 1024.0 high bytes
    unsigned int off_bits = 0x64006400u;          // half2 {1024, 1024}
    __half2 off2 = *reinterpret_cast<__half2*>(&off_bits);

    float acc = 0.0f;
    #pragma unroll 4
    for (int s = s_start; s < s1; s += 4) {
        int ix = __float2int_rd(X);
        int iy = __float2int_rd(Y);
        float fx = X - (float)ix;
        float fy = Y - (float)iy;
        X += Bx4;
        Y += By4;
        unsigned int q = __ldg(&g_quad[iy * TAB_N + ix]);
        // h0 = {1024+b00, 1024+b01}, h1 = {1024+b10, 1024+b11}
        unsigned int u0 = __byte_perm(q, MAGIC, 0x4140);
        unsigned int u1 = __byte_perm(q, MAGIC, 0x4342);
        __half2 h0 = *reinterpret_cast<__half2*>(&u0);
        __half2 h1 = *reinterpret_cast<__half2*>(&u1);
        __half2 base = __hsub2(h0, off2);       // {b00, b01} exact
        __half2 dv2  = __hsub2(h1, h0);         // {b10-b00, b11-b01} exact
        __half2 fxy  = __floats2half2_rn(fx, fy);   // {fx, fy}
        __half2 va   = __hfma2(__high2half2(fxy), dv2, base);  // {vl, vr}
        __half  dh   = __hsub(__high2half(va), __low2half(va));
        __half  vh   = __hfma(__low2half(fxy), dh, __low2half(va));
        acc += __half2float(vh);
    }

    // Reduce over the 4 phase lanes (stride 8, 16)
    acc += __shfl_xor_sync(0xFFFFFFFFu, acc, 8);
    acc += __shfl_xor_sync(0xFFFFFFFFu, acc, 16);

    if (p == 0) {
        out[(N_ANGLES - 1 - a) * DET_COUNT + (DET_COUNT - 1 - d)] =
            acc * (1.0f / (255.0f * N_SAMP));
    }
}

extern "C" void kernel_launch(void* const* d_in, const int* in_sizes, int n_in,
                              void* d_out, int out_size) {
    const float* img = (const float*)d_in[0];
    float* out = (float*)d_out;

    int tab_elems = TAB_N * TAB_N;
    build_quad_kernel<<<(tab_elems + 255) / 256, 256>>>(img);

    int total = N_ANGLES * DET_COUNT * 4;   // 4 phases per (angle, detector)
    radon_kernel<<<total / 256, 256>>>(out);
}

// round 15
// speedup vs baseline: 1.0012x; 1.0012x over previous
#include <cuda_runtime.h>
#include <cuda_fp16.h>
#include <math.h>

// Problem constants (fixed shapes)
#define IMG_N     512
#define N_ANGLES  512
#define DET_COUNT 512
#define N_SAMP    256

// u8 quad table, row-major. Table coord tx in [0,528): floor-cell real-x = tx - 6.
// quad(ty,tx) = bytes {b00, b01, b10, b11} = round(P*255) of the 2x2 corners,
// P = image with zeros outside [0,512)^2. Nonzero quads live at tx in [5,517];
// the >=5-cell zero guard on each side absorbs clip slack (max 1 sample step
// = 2.83 cells past the clip window) with no per-sample clamp or mask.
#define TAB_N     528
#define OFF       6.0f
__device__ unsigned int g_quad[TAB_N * TAB_N];

__global__ void build_quad_kernel(const float* __restrict__ img) {
    int i = blockIdx.x * blockDim.x + threadIdx.x;
    if (i >= TAB_N * TAB_N) return;
    int tx = i % TAB_N;
    int ty = i / TAB_N;
    int ix = tx - 6;                  // real-coord floor cell
    int iy = ty - 6;
    unsigned int b[2][2];
    #pragma unroll
    for (int r = 0; r < 2; ++r)
        #pragma unroll
        for (int c = 0; c < 2; ++c) {
            int ry = iy + r;
            int rx = ix + c;
            float v = ((unsigned)ry < (unsigned)IMG_N && (unsigned)rx < (unsigned)IMG_N)
                          ? __ldg(&img[ry * IMG_N + rx]) : 0.0f;
            b[r][c] = __float2uint_rn(v * 255.0f);
        }
    g_quad[i] = b[0][0] | (b[0][1] << 8) | (b[1][0] << 16) | (b[1][1] << 24);
}

// Warp shape: 8 detectors x 4 sample-phases. lane = p*8 + d_off.
// Thread accumulates samples s ≡ p (mod 4); butterfly-reduce over phases at end.
__global__ __launch_bounds__(256)
void radon_kernel(float* __restrict__ out) {
    int idx  = blockIdx.x * blockDim.x + threadIdx.x;   // 0 .. 4*512*512-1
    int lane = idx & 31;
    int w    = idx >> 5;
    int p    = lane >> 3;
    int a    = w >> 6;
    int d    = ((w & 63) << 3) | (lane & 7);

    const float PI_F    = 3.14159265358979323846f;
    const float SQRT2_F = 1.41421356237309504880f;

    float ang = a * (PI_F / (N_ANGLES - 1)) + 0.5f * PI_F;
    float sa, ca;
    sincosf(ang, &sa, &ca);

    float sx = -1.0f + d * (2.0f / (DET_COUNT - 1));
    const float sy = -SQRT2_F;

    float rsx = sx * ca - sy * sa;
    float rsy = sx * sa + sy * ca;
    float rdx = 2.0f * sy * sa;
    float rdy = -2.0f * sy * ca;

    const float HALF = 0.5f * (IMG_N - 1);   // 255.5
    float Ax = (rsx + 1.0f) * HALF + OFF;
    float Ay = (rsy + 1.0f) * HALF + OFF;
    float Bx = rdx * (HALF / N_SAMP);
    float By = rdy * (HALF / N_SAMP);

    // Clip to nonzero region: real x in (-1,512) => X in (5, 518) table coords.
    float slo = 0.0f, shi = (float)N_SAMP;
    {
        const float LO = 5.0f, HI = 518.0f;
        if (fabsf(Bx) > 1e-12f) {
            float inv = __fdividef(1.0f, Bx);
            float t1 = (LO - Ax) * inv;
            float t2 = (HI - Ax) * inv;
            slo = fmaxf(slo, fminf(t1, t2));
            shi = fminf(shi, fmaxf(t1, t2));
        } else if (Ax <= LO || Ax >= HI) {
            shi = slo;
        }
        if (fabsf(By) > 1e-12f) {
            float inv = __fdividef(1.0f, By);
            float t1 = (LO - Ay) * inv;
            float t2 = (HI - Ay) * inv;
            slo = fmaxf(slo, fminf(t1, t2));
            shi = fminf(shi, fmaxf(t1, t2));
        } else if (Ay <= LO || Ay >= HI) {
            shi = slo;
        }
    }
    int s0 = max(0, (int)ceilf(slo - 1.0f));
    int s1 = min(N_SAMP, (int)floorf(shi + 1.0f) + 1);

    // First sample for this phase: s ≡ p (mod 4), s >= s0
    int s_start = s0 + ((p - s0) & 3);

    // Incremental ray position (step = 4 samples)
    float X = fmaf((float)s_start, Bx, Ax);
    float Y = fmaf((float)s_start, By, Ay);
    float Bx4 = 4.0f * Bx;
    float By4 = 4.0f * By;

    const unsigned int MAGIC = 0x64646464u;       // fp16 1024.0 high bytes
    unsigned int off_bits = 0x64006400u;          // half2 {1024, 1024}
    __half2 off2 = *reinterpret_cast<__half2*>(&off_bits);

    float acc = 0.0f;
    #pragma unroll 4
    for (int s = s_start; s < s1; s += 4) {
        int ix = __float2int_rd(X);
        int iy = __float2int_rd(Y);
        float fx = X - (float)ix;
        float fy = Y - (float)iy;
        X += Bx4;
        Y += By4;
        unsigned int q = __ldg(&g_quad[iy * TAB_N + ix]);
        // h0 = {1024+b00, 1024+b01}, h1 = {1024+b10, 1024+b11}
        unsigned int u0 = __byte_perm(q, MAGIC, 0x4140);
        unsigned int u1 = __byte_perm(q, MAGIC, 0x4342);
        __half2 h0 = *reinterpret_cast<__half2*>(&u0);
        __half2 h1 = *reinterpret_cast<__half2*>(&u1);
        __half2 base = __hsub2(h0, off2);       // {b00, b01} exact
        __half2 dv2  = __hsub2(h1, h0);         // {b10-b00, b11-b01} exact
        __half2 fxy  = __floats2half2_rn(fx, fy);   // {fx, fy}
        __half2 va   = __hfma2(__high2half2(fxy), dv2, base);  // {vl, vr}
        __half  dh   = __hsub(__high2half(va), __low2half(va));
        __half  vh   = __hfma(__low2half(fxy), dh, __low2half(va));
        acc += __half2float(vh);
    }

    // Reduce over the 4 phase lanes (stride 8, 16)
    acc += __shfl_xor_sync(0xFFFFFFFFu, acc, 8);
    acc += __shfl_xor_sync(0xFFFFFFFFu, acc, 16);

    if (p == 0) {
        out[(N_ANGLES - 1 - a) * DET_COUNT + (DET_COUNT - 1 - d)] =
            acc * (1.0f / (255.0f * N_SAMP));
    }
}

extern "C" void kernel_launch(void* const* d_in, const int* in_sizes, int n_in,
                              void* d_out, int out_size) {
    const float* img = (const float*)d_in[0];
    float* out = (float*)d_out;

    int tab_elems = TAB_N * TAB_N;
    build_quad_kernel<<<(tab_elems + 255) / 256, 256>>>(img);

    int total = N_ANGLES * DET_COUNT * 4;   // 4 phases per (angle, detector)
    radon_kernel<<<total / 256, 256>>>(out);
}